// round 15
// baseline (speedup 1.0000x reference)
#include <cuda_runtime.h>
#include <cuda.h>
#include <cstdint>
#include <math.h>

// SpatialGlimpse fused, one-shot blocks, two-phase separable stencil.
// R15: staging = ONE 4D TMA tensormap load per block (box [12,G,9,1] over the
// image viewed as [12, 128, 512, 64] f32). Kills the 9-request-per-block
// serialization (~500ns each) that pinned DRAM at 2.5-2.8 TB/s since R3.
// TMA OOB zero-fill removes all tail/OOB zeroing. Shape: NT=128, JW=32, 7168 blocks.

static constexpr int BATCH  = 64;
static constexpr int H = 512, W = 512, C = 3;
static constexpr int OUTHW  = 64;
static constexpr int NDEPTH = 3;
static constexpr int NT     = 128;
static constexpr int JW     = 32;      // output columns per block (all depths)
static constexpr int IR     = 9;       // input rows per tile (all depths)

// G = 12-float groups per tile row (TMA box dim1). Extent needed:
// off0(<=9) + 3*K*(JW-1) + 3K+3  ->  K4: 396<=408(G34), K2: 204<=216(G18), K1: 108<=120(G10).
template<int K> struct Cfg;
template<> struct Cfg<1> { static constexpr int TILE_I = 8; static constexpr int G = 10; static constexpr int NV = 3; };
template<> struct Cfg<2> { static constexpr int TILE_I = 4; static constexpr int G = 18; static constexpr int NV = 3; };
template<> struct Cfg<4> { static constexpr int TILE_I = 2; static constexpr int G = 34; static constexpr int NV = 5; };

static constexpr int NBLK4 = BATCH * 32 * 2;   // 4096
static constexpr int NBLK2 = BATCH * 16 * 2;   // 2048
static constexpr int NBLK1 = BATCH * 8 * 2;    // 1024
static constexpr int NBLK  = NBLK4 + NBLK2 + NBLK1;   // 7168

// SMEM floats: tile (max 9*408=3672) | mbar (idx 3672, 16B-aligned) | hs 9*32 f4
static constexpr int MBAR_OFF    = 3672;
static constexpr int HS_OFF      = 3676;
static constexpr int SMEM_FLOATS = HS_OFF + IR * JW * 4;   // 4828
static constexpr int SMEM_BYTES  = SMEM_FLOATS * 4;        // 19312

__device__ __forceinline__ uint32_t smem_u32(const void* p) {
    return (uint32_t)__cvta_generic_to_shared(p);
}
__device__ __forceinline__ void mbar_init(uint32_t a, uint32_t cnt) {
    asm volatile("mbarrier.init.shared.b64 [%0], %1;" :: "r"(a), "r"(cnt) : "memory");
}
__device__ __forceinline__ void mbar_expect_tx(uint32_t a, uint32_t bytes) {
    asm volatile("mbarrier.arrive.expect_tx.shared.b64 _, [%0], %1;" :: "r"(a), "r"(bytes) : "memory");
}
__device__ __forceinline__ void mbar_wait(uint32_t a, uint32_t parity) {
    asm volatile(
        "{\n\t"
        ".reg .pred P;\n\t"
        "LAB_WAIT_%=:\n\t"
        "mbarrier.try_wait.parity.acquire.cta.shared::cta.b64 P, [%0], %1, 0x989680;\n\t"
        "@P bra LAB_DONE_%=;\n\t"
        "bra LAB_WAIT_%=;\n\t"
        "LAB_DONE_%=:\n\t"
        "}"
        :: "r"(a), "r"(parity) : "memory");
}
__device__ __forceinline__ void tma_load_4d(const CUtensorMap* m, uint32_t dst,
                                            int c0, int c1, int c2, int c3, uint32_t mbar)
{
    asm volatile(
        "cp.async.bulk.tensor.4d.shared::cta.global.tile.mbarrier::complete_tx::bytes "
        "[%0], [%1, {%2, %3, %4, %5}], [%6];"
        :: "r"(dst), "l"(m), "r"(c0), "r"(c1), "r"(c2), "r"(c3), "r"(mbar) : "memory");
}

// Horizontal weighted sum of one row window (K+1 pixels x 3 channels).
// SH = sub-float4 shift (compile-time so v[] stays in registers).
template<int K, int SH>
__device__ __forceinline__ void hreduce_one(const float* __restrict__ rowp, float wx, float4& h)
{
    constexpr int NV = Cfg<K>::NV;
    const float hx0 = 1.0f - wx;
    float v[4 * NV];
    const float4* rp = reinterpret_cast<const float4*>(rowp);
#pragma unroll
    for (int t = 0; t < NV; t++) {
        float4 q = rp[t];
        v[4*t+0] = q.x; v[4*t+1] = q.y; v[4*t+2] = q.z; v[4*t+3] = q.w;
    }
    float r0 = hx0 * v[SH + 0] + wx * v[SH + 3*K + 0];
    float r1 = hx0 * v[SH + 1] + wx * v[SH + 3*K + 1];
    float r2 = hx0 * v[SH + 2] + wx * v[SH + 3*K + 2];
#pragma unroll
    for (int q = 1; q < K; q++) {
        r0 += v[SH + 3*q + 0];
        r1 += v[SH + 3*q + 1];
        r2 += v[SH + 3*q + 2];
    }
    h.x = r0; h.y = r1; h.z = r2; h.w = 0.0f;
}

template<int K, int D>
__device__ __forceinline__ void glimpse_body(
    const CUtensorMap* __restrict__ tmap, const float* __restrict__ offs,
    float* __restrict__ out, float* smem, int b, int i0, int j0)
{
    constexpr int TILE_I = Cfg<K>::TILE_I;
    constexpr int G      = Cfg<K>::G;
    constexpr int RT     = 12 * G;              // tile row pitch (floats)

    float* tile = smem;
    float4* hs  = reinterpret_cast<float4*>(smem + HS_OFF);
    const uint32_t mbar = smem_u32(smem + MBAR_OFF);
    const int tid = threadIdx.x;

    // Geometry (all threads; fp32 ops match reference rounding — proven rel_err 7e-8).
    const float cy = (offs[2*b + 0] + 1.0f) * (H * 0.5f);
    const float cx = (offs[2*b + 1] + 1.0f) * (W * 0.5f);
    const float Ey = cy - (OUTHW * K - 1) * 0.5f;
    const float Ex = cx - (OUTHW * K - 1) * 0.5f;
    const int   y0 = (int)floorf(Ey);
    const int   x0 = (int)floorf(Ex);
    const float wy = Ey - (float)y0;
    const float wx = Ex - (float)x0;

    const int px0  = x0 + j0 * K;               // >= 0 for these shapes
    const int g0   = px0 >> 2;                  // start 12-float group (px0*3/12)
    const int off0 = 3 * (px0 & 3);             // 0/3/6/9
    const int ytop = y0 + i0 * K;               // y-OOB rows -> TMA zero-fill

    // ── Stage: ONE 4D TMA request for the whole tile. OOB (x and y) zero-filled. ──
    if (tid == 0) {
        mbar_init(mbar, 1);
        asm volatile("fence.proxy.async.shared::cta;" ::: "memory");
        mbar_expect_tx(mbar, (uint32_t)(G * 12 * IR * 4));
        tma_load_4d(tmap, smem_u32(tile), 0, g0, ytop, b, mbar);
    }
    __syncthreads();                 // mbar init visible to warp 0
    if (tid < 32) mbar_wait(mbar, 0);
    __syncthreads();

    // ── Phase A: horizontal (K+1)-tap sums; 288 items over 128 threads.
    //    Lane word-stride 3K -> conflict-free LDS.128; shift hoisted per thread. ──
    {
        const int jA   = tid & 31;
        const int sidx = off0 + 3 * K * jA;
        const float* colp = tile + (sidx & ~3);
        const int sh = sidx & 3;
#pragma unroll
        for (int it = 0; it < 3; it++) {
            const int r = (tid >> 5) + it * 4;
            if (r < IR) {
                const float* rowp = colp + r * RT;
                float4 h;
                switch (sh) {
                case 0:  hreduce_one<K,0>(rowp, wx, h); break;
                case 1:  hreduce_one<K,1>(rowp, wx, h); break;
                case 2:  hreduce_one<K,2>(rowp, wx, h); break;
                default: hreduce_one<K,3>(rowp, wx, h); break;
                }
                hs[r * JW + jA] = h;
            }
        }
    }
    __syncthreads();

    // ── Phase B: vertical (K+1)-tap over hs. Conflict-free. ──
    constexpr float inv = 1.0f / (K * K);
    const float wy0 = 1.0f - wy;
    for (int o = tid; o < TILE_I * JW; o += NT) {
        const int ti = o >> 5;
        const int jj = o & 31;
        float4 a = hs[(ti * K) * JW + jj];
        float o0 = wy0 * a.x, o1 = wy0 * a.y, o2 = wy0 * a.z;
#pragma unroll
        for (int p = 1; p < K; p++) {
            float4 m = hs[(ti * K + p) * JW + jj];
            o0 += m.x; o1 += m.y; o2 += m.z;
        }
        float4 e = hs[(ti * K + K) * JW + jj];
        o0 += wy * e.x; o1 += wy * e.y; o2 += wy * e.z;

        const size_t ob = (((size_t)b * OUTHW + (i0 + ti)) * OUTHW + (j0 + jj)) * (C * NDEPTH);
        out[ob + 0 * NDEPTH + D] = o0 * inv;
        out[ob + 1 * NDEPTH + D] = o1 * inv;
        out[ob + 2 * NDEPTH + D] = o2 * inv;
    }
}

__global__ __launch_bounds__(NT, 9)
void glimpse_fused(const __grid_constant__ CUtensorMap t4,
                   const __grid_constant__ CUtensorMap t2,
                   const __grid_constant__ CUtensorMap t1,
                   const float* __restrict__ offs, float* __restrict__ out)
{
    extern __shared__ __align__(128) float smem[];
    const int bid = blockIdx.x;
    if (bid < NBLK4) {                       // K=4: 64 blocks/image (32 row x 2 col)
        const int b = bid >> 6;
        const int t = bid & 63;
        glimpse_body<4, 2>(&t4, offs, out, smem, b, (t >> 1) * 2, (t & 1) * JW);
    } else if (bid < NBLK4 + NBLK2) {        // K=2: 32 blocks/image (16 row x 2 col)
        const int r = bid - NBLK4;
        const int b = r >> 5;
        const int t = r & 31;
        glimpse_body<2, 1>(&t2, offs, out, smem, b, (t >> 1) * 4, (t & 1) * JW);
    } else {                                 // K=1: 16 blocks/image (8 row x 2 col)
        const int r = bid - (NBLK4 + NBLK2);
        const int b = r >> 4;
        const int t = r & 15;
        glimpse_body<1, 0>(&t1, offs, out, smem, b, (t >> 1) * 8, (t & 1) * JW);
    }
}

typedef CUresult (*EncodeFn)(
    CUtensorMap*, CUtensorMapDataType, cuuint32_t, void*,
    const cuuint64_t*, const cuuint64_t*, const cuuint32_t*, const cuuint32_t*,
    CUtensorMapInterleave, CUtensorMapSwizzle, CUtensorMapL2promotion, CUtensorMapFloatOOBfill);

extern "C" void kernel_launch(void* const* d_in, const int* in_sizes, int n_in,
                              void* d_out, int out_size)
{
    (void)in_sizes; (void)n_in; (void)out_size;
    void* img = d_in[0];
    const float* offs = (const float*)d_in[1];
    float* out = (float*)d_out;

    // Resolve cuTensorMapEncodeTiled through the runtime (no -lcuda link needed).
    void* sym = nullptr;
    cudaDriverEntryPointQueryResult qres = cudaDriverEntryPointSuccess;
#if CUDART_VERSION >= 12050
    cudaGetDriverEntryPointByVersion("cuTensorMapEncodeTiled", &sym, 12000,
                                     cudaEnableDefault, &qres);
#else
    cudaGetDriverEntryPoint("cuTensorMapEncodeTiled", &sym, cudaEnableDefault, &qres);
#endif
    EncodeFn enc = (EncodeFn)sym;

    // Image viewed as [12 floats, 128 groups, 512 rows, 64 imgs] (1536 = 12*128).
    CUtensorMap t4, t2, t1;
    cuuint64_t gdim[4] = {12, 128, 512, 64};
    cuuint64_t gstr[3] = {48, 6144, 3145728};          // bytes; multiples of 16
    cuuint32_t estr[4] = {1, 1, 1, 1};
    cuuint32_t box[4]  = {12, (cuuint32_t)Cfg<4>::G, 9, 1};
    enc(&t4, CU_TENSOR_MAP_DATA_TYPE_FLOAT32, 4, img, gdim, gstr, box, estr,
        CU_TENSOR_MAP_INTERLEAVE_NONE, CU_TENSOR_MAP_SWIZZLE_NONE,
        CU_TENSOR_MAP_L2_PROMOTION_L2_128B, CU_TENSOR_MAP_FLOAT_OOB_FILL_NONE);
    box[1] = (cuuint32_t)Cfg<2>::G;
    enc(&t2, CU_TENSOR_MAP_DATA_TYPE_FLOAT32, 4, img, gdim, gstr, box, estr,
        CU_TENSOR_MAP_INTERLEAVE_NONE, CU_TENSOR_MAP_SWIZZLE_NONE,
        CU_TENSOR_MAP_L2_PROMOTION_L2_128B, CU_TENSOR_MAP_FLOAT_OOB_FILL_NONE);
    box[1] = (cuuint32_t)Cfg<1>::G;
    enc(&t1, CU_TENSOR_MAP_DATA_TYPE_FLOAT32, 4, img, gdim, gstr, box, estr,
        CU_TENSOR_MAP_INTERLEAVE_NONE, CU_TENSOR_MAP_SWIZZLE_NONE,
        CU_TENSOR_MAP_L2_PROMOTION_L2_128B, CU_TENSOR_MAP_FLOAT_OOB_FILL_NONE);

    cudaFuncSetAttribute(glimpse_fused, cudaFuncAttributeMaxDynamicSharedMemorySize, SMEM_BYTES);
    glimpse_fused<<<NBLK, NT, SMEM_BYTES>>>(t4, t2, t1, offs, out);
}

// round 17
// speedup vs baseline: 1.1503x; 1.1503x over previous
#include <cuda_runtime.h>
#include <cuda.h>
#include <cstdint>
#include <math.h>

// SpatialGlimpse, depth-fused blocks, two-phase separable stencil.
// R17 = R16 (one block computes K=4,2,1 for the same output tile; 9 floats per
// pixel assembled in SMEM; dense STG.128 output) with TMA SMEM destinations
// padded to 128-byte alignment (R16's "misaligned address" root cause).

static constexpr int BATCH  = 64;
static constexpr int H = 512, W = 512, C = 3;
static constexpr int OUTHW  = 64;
static constexpr int NDEPTH = 3;
static constexpr int NT     = 128;
static constexpr int JW     = 32;     // output columns per block
static constexpr int TI     = 2;      // output rows per block

template<int K> struct Cfg;          // G = 12-float groups per tile row; ROWS = TI*K+1
template<> struct Cfg<1> { static constexpr int G = 10; static constexpr int ROWS = 3; static constexpr int NV = 3; };
template<> struct Cfg<2> { static constexpr int G = 18; static constexpr int ROWS = 5; static constexpr int NV = 3; };
template<> struct Cfg<4> { static constexpr int G = 34; static constexpr int ROWS = 9; static constexpr int NV = 5; };
// extent check: off0(<=9) + 3K*(JW-1) + 3K+3 -> K4 396<=408, K2 204<=216, K1 108<=120.

static constexpr int NBLK = BATCH * 32 * 2;   // 4096 (32 row-pairs x 2 col-halves)

// SMEM float offsets — all TMA destinations on 128B (32-float) boundaries.
static constexpr int T4_OFF = 0;                    // 9*408 = 3672 floats
static constexpr int T2_OFF = 3680;                 // 128B-aligned; 5*216 = 1080 -> 4760
static constexpr int T1_OFF = 4768;                 // 128B-aligned; 3*120 = 360 -> 5128
static constexpr int MB_OFF = 5128;                 // 3 mbars (8B) at floats 5128/5130/5132
static constexpr int HS_OFF = 5136;                 // 16B-aligned; 9*32 f4 = 1152 floats
static constexpr int OB_OFF = 6288;                 // outbuf 2*32*9 = 576 floats
static constexpr int SMEM_FLOATS = 6864;
static constexpr int SMEM_BYTES  = SMEM_FLOATS * 4; // 27456

__device__ __forceinline__ uint32_t smem_u32(const void* p) {
    return (uint32_t)__cvta_generic_to_shared(p);
}
__device__ __forceinline__ void mbar_init(uint32_t a, uint32_t cnt) {
    asm volatile("mbarrier.init.shared.b64 [%0], %1;" :: "r"(a), "r"(cnt) : "memory");
}
__device__ __forceinline__ void mbar_expect_tx(uint32_t a, uint32_t bytes) {
    asm volatile("mbarrier.arrive.expect_tx.shared.b64 _, [%0], %1;" :: "r"(a), "r"(bytes) : "memory");
}
__device__ __forceinline__ void mbar_wait(uint32_t a, uint32_t parity) {
    asm volatile(
        "{\n\t"
        ".reg .pred P;\n\t"
        "LAB_WAIT_%=:\n\t"
        "mbarrier.try_wait.parity.acquire.cta.shared::cta.b64 P, [%0], %1, 0x989680;\n\t"
        "@P bra LAB_DONE_%=;\n\t"
        "bra LAB_WAIT_%=;\n\t"
        "LAB_DONE_%=:\n\t"
        "}"
        :: "r"(a), "r"(parity) : "memory");
}
__device__ __forceinline__ void tma_load_4d(const CUtensorMap* m, uint32_t dst,
                                            int c0, int c1, int c2, int c3, uint32_t mbar)
{
    asm volatile(
        "cp.async.bulk.tensor.4d.shared::cta.global.tile.mbarrier::complete_tx::bytes "
        "[%0], [%1, {%2, %3, %4, %5}], [%6];"
        :: "r"(dst), "l"(m), "r"(c0), "r"(c1), "r"(c2), "r"(c3), "r"(mbar) : "memory");
}

// Horizontal weighted sum of one row window (K+1 pixels x 3 channels).
template<int K, int SH>
__device__ __forceinline__ void hreduce_one(const float* __restrict__ rowp, float wx, float4& h)
{
    constexpr int NV = Cfg<K>::NV;
    const float hx0 = 1.0f - wx;
    float v[4 * NV];
    const float4* rp = reinterpret_cast<const float4*>(rowp);
#pragma unroll
    for (int t = 0; t < NV; t++) {
        float4 q = rp[t];
        v[4*t+0] = q.x; v[4*t+1] = q.y; v[4*t+2] = q.z; v[4*t+3] = q.w;
    }
    float r0 = hx0 * v[SH + 0] + wx * v[SH + 3*K + 0];
    float r1 = hx0 * v[SH + 1] + wx * v[SH + 3*K + 1];
    float r2 = hx0 * v[SH + 2] + wx * v[SH + 3*K + 2];
#pragma unroll
    for (int q = 1; q < K; q++) {
        r0 += v[SH + 3*q + 0];
        r1 += v[SH + 3*q + 1];
        r2 += v[SH + 3*q + 2];
    }
    h.x = r0; h.y = r1; h.z = r2; h.w = 0.0f;
}

// Phase A + Phase B for one depth; results go to outbuf (stride-9 STS, conflict-free).
template<int K, int D>
__device__ __forceinline__ void depth_compute(
    const float* __restrict__ tile, float4* __restrict__ hs, float* __restrict__ outbuf,
    int off0, float wx, float wy)
{
    constexpr int G    = Cfg<K>::G;
    constexpr int ROWS = Cfg<K>::ROWS;
    constexpr int RT   = 12 * G;
    const int tid = threadIdx.x;

    // Phase A: ROWS*32 windows; lane word-stride 3K -> conflict-free LDS.128.
    {
        const int jA   = tid & 31;
        const int sidx = off0 + 3 * K * jA;
        const float* colp = tile + (sidx & ~3);
        const int sh = sidx & 3;
        for (int idx = tid; idx < ROWS * 32; idx += NT) {   // jA invariant (NT%32==0)
            const int r = idx >> 5;
            const float* rowp = colp + r * RT;
            float4 h;
            switch (sh) {
            case 0:  hreduce_one<K,0>(rowp, wx, h); break;
            case 1:  hreduce_one<K,1>(rowp, wx, h); break;
            case 2:  hreduce_one<K,2>(rowp, wx, h); break;
            default: hreduce_one<K,3>(rowp, wx, h); break;
            }
            hs[r * 32 + jA] = h;
        }
    }
    __syncthreads();

    // Phase B: TI*32 = 64 outputs -> outbuf[pix][c*3+D].
    if (tid < TI * 32) {
        const int ti = tid >> 5, jj = tid & 31;
        const float wy0 = 1.0f - wy;
        float4 a = hs[(ti * K) * 32 + jj];
        float o0 = wy0 * a.x, o1 = wy0 * a.y, o2 = wy0 * a.z;
#pragma unroll
        for (int p = 1; p < K; p++) {
            float4 m = hs[(ti * K + p) * 32 + jj];
            o0 += m.x; o1 += m.y; o2 += m.z;
        }
        float4 e = hs[(ti * K + K) * 32 + jj];
        o0 += wy * e.x; o1 += wy * e.y; o2 += wy * e.z;
        constexpr float inv = 1.0f / (K * K);
        float* ob = outbuf + (ti * 32 + jj) * 9 + D;
        ob[0] = o0 * inv; ob[3] = o1 * inv; ob[6] = o2 * inv;
    }
    __syncthreads();   // hs reuse + outbuf ordering
}

struct Geom { float wy, wx; int off0, g0, ytop; };
template<int K>
__device__ __forceinline__ Geom geom(float cy, float cx, int i0, int j0)
{
    const float Ey = cy - (OUTHW * K - 1) * 0.5f;
    const float Ex = cx - (OUTHW * K - 1) * 0.5f;
    const int y0 = (int)floorf(Ey);
    const int x0 = (int)floorf(Ex);
    Geom g;
    g.wy = Ey - (float)y0;
    g.wx = Ex - (float)x0;
    const int px0 = x0 + j0 * K;          // >= 0 for these shapes
    g.g0   = px0 >> 2;                    // 12-float group index (px0*3/12)
    g.off0 = 3 * (px0 & 3);               // 0/3/6/9
    g.ytop = y0 + i0 * K;                 // bottom OOB rows -> TMA zero-fill
    return g;
}

__global__ __launch_bounds__(NT, 8)
void glimpse_fused(const __grid_constant__ CUtensorMap t4,
                   const __grid_constant__ CUtensorMap t2,
                   const __grid_constant__ CUtensorMap t1,
                   const float* __restrict__ offs, float* __restrict__ out)
{
    extern __shared__ __align__(128) float smem[];
    const int bid = blockIdx.x;
    const int b   = bid >> 6;
    const int t   = bid & 63;
    const int i0  = (t >> 1) * TI;
    const int j0  = (t & 1) * JW;
    const int tid = threadIdx.x;

    const float cy = (offs[2*b + 0] + 1.0f) * (H * 0.5f);
    const float cx = (offs[2*b + 1] + 1.0f) * (W * 0.5f);
    const Geom g4 = geom<4>(cy, cx, i0, j0);
    const Geom g2 = geom<2>(cy, cx, i0, j0);
    const Geom g1 = geom<1>(cy, cx, i0, j0);

    const uint32_t mb0 = smem_u32(smem + MB_OFF);
    const uint32_t mb1 = smem_u32(smem + MB_OFF + 2);
    const uint32_t mb2 = smem_u32(smem + MB_OFF + 4);
    float4* hs     = reinterpret_cast<float4*>(smem + HS_OFF);
    float*  outbuf = smem + OB_OFF;

    if (tid == 0) {
        mbar_init(mb0, 1); mbar_init(mb1, 1); mbar_init(mb2, 1);
        asm volatile("fence.proxy.async.shared::cta;" ::: "memory");
        mbar_expect_tx(mb0, (uint32_t)(Cfg<4>::G * 12 * Cfg<4>::ROWS * 4));
        tma_load_4d(&t4, smem_u32(smem + T4_OFF), 0, g4.g0, g4.ytop, b, mb0);
        mbar_expect_tx(mb1, (uint32_t)(Cfg<2>::G * 12 * Cfg<2>::ROWS * 4));
        tma_load_4d(&t2, smem_u32(smem + T2_OFF), 0, g2.g0, g2.ytop, b, mb1);
        mbar_expect_tx(mb2, (uint32_t)(Cfg<1>::G * 12 * Cfg<1>::ROWS * 4));
        tma_load_4d(&t1, smem_u32(smem + T1_OFF), 0, g1.g0, g1.ytop, b, mb2);
    }
    __syncthreads();   // mbar inits visible

    mbar_wait(mb0, 0);
    depth_compute<4, 2>(smem + T4_OFF, hs, outbuf, g4.off0, g4.wx, g4.wy);
    mbar_wait(mb1, 0);
    depth_compute<2, 1>(smem + T2_OFF, hs, outbuf, g2.off0, g2.wx, g2.wy);
    mbar_wait(mb2, 0);
    depth_compute<1, 0>(smem + T1_OFF, hs, outbuf, g1.off0, g1.wx, g1.wy);

    // ── Dense output: 2 rows x 288 contiguous floats = 2 x 72 STG.128.
    //    outBase is a multiple of 288 floats (j0 in {0,32} -> 32*9), so
    //    float4 alignment holds; row stride 64*9=576 floats also aligned. ──
    const size_t outBase = (((size_t)b * OUTHW + i0) * OUTHW + j0) * (C * NDEPTH);
    for (int f = tid; f < 2 * 72; f += NT) {
        const int ti = f / 72, fi = f - ti * 72;
        reinterpret_cast<float4*>(out + outBase + (size_t)ti * (OUTHW * 9))[fi] =
            reinterpret_cast<const float4*>(outbuf + ti * 288)[fi];
    }
}

typedef CUresult (*EncodeFn)(
    CUtensorMap*, CUtensorMapDataType, cuuint32_t, void*,
    const cuuint64_t*, const cuuint64_t*, const cuuint32_t*, const cuuint32_t*,
    CUtensorMapInterleave, CUtensorMapSwizzle, CUtensorMapL2promotion, CUtensorMapFloatOOBfill);

extern "C" void kernel_launch(void* const* d_in, const int* in_sizes, int n_in,
                              void* d_out, int out_size)
{
    (void)in_sizes; (void)n_in; (void)out_size;
    void* img = d_in[0];
    const float* offs = (const float*)d_in[1];
    float* out = (float*)d_out;

    void* sym = nullptr;
    cudaDriverEntryPointQueryResult qres = cudaDriverEntryPointSuccess;
#if CUDART_VERSION >= 12050
    cudaGetDriverEntryPointByVersion("cuTensorMapEncodeTiled", &sym, 12000,
                                     cudaEnableDefault, &qres);
#else
    cudaGetDriverEntryPoint("cuTensorMapEncodeTiled", &sym, cudaEnableDefault, &qres);
#endif
    EncodeFn enc = (EncodeFn)sym;

    // Image viewed as [12 floats, 128 groups, 512 rows, 64 imgs] (1536 = 12*128).
    CUtensorMap t4, t2, t1;
    cuuint64_t gdim[4] = {12, 128, 512, 64};
    cuuint64_t gstr[3] = {48, 6144, 3145728};
    cuuint32_t estr[4] = {1, 1, 1, 1};

    cuuint32_t box4[4] = {12, (cuuint32_t)Cfg<4>::G, (cuuint32_t)Cfg<4>::ROWS, 1};
    enc(&t4, CU_TENSOR_MAP_DATA_TYPE_FLOAT32, 4, img, gdim, gstr, box4, estr,
        CU_TENSOR_MAP_INTERLEAVE_NONE, CU_TENSOR_MAP_SWIZZLE_NONE,
        CU_TENSOR_MAP_L2_PROMOTION_L2_128B, CU_TENSOR_MAP_FLOAT_OOB_FILL_NONE);
    cuuint32_t box2[4] = {12, (cuuint32_t)Cfg<2>::G, (cuuint32_t)Cfg<2>::ROWS, 1};
    enc(&t2, CU_TENSOR_MAP_DATA_TYPE_FLOAT32, 4, img, gdim, gstr, box2, estr,
        CU_TENSOR_MAP_INTERLEAVE_NONE, CU_TENSOR_MAP_SWIZZLE_NONE,
        CU_TENSOR_MAP_L2_PROMOTION_L2_128B, CU_TENSOR_MAP_FLOAT_OOB_FILL_NONE);
    cuuint32_t box1[4] = {12, (cuuint32_t)Cfg<1>::G, (cuuint32_t)Cfg<1>::ROWS, 1};
    enc(&t1, CU_TENSOR_MAP_DATA_TYPE_FLOAT32, 4, img, gdim, gstr, box1, estr,
        CU_TENSOR_MAP_INTERLEAVE_NONE, CU_TENSOR_MAP_SWIZZLE_NONE,
        CU_TENSOR_MAP_L2_PROMOTION_L2_128B, CU_TENSOR_MAP_FLOAT_OOB_FILL_NONE);

    cudaFuncSetAttribute(glimpse_fused, cudaFuncAttributeMaxDynamicSharedMemorySize, SMEM_BYTES);
    glimpse_fused<<<NBLK, NT, SMEM_BYTES>>>(t4, t2, t1, offs, out);
}